// round 15
// baseline (speedup 1.0000x reference)
#include <cuda_runtime.h>
#include <cuda_fp16.h>
#include <cstdint>

#define BB 16
#define NN 1024
#define MM 12
#define FA 128
#define FO 128

// Scratch (allocation-free rule: __device__ globals)
__device__ float  g_bn3[BB * NN];
__device__ float  g_bn6[BB * NN];
__device__ __half g_atom_h[BB * NN * FA];   // 4 MB fp16 copy of atom
__device__ __half g_Wh[FA * FO];            // fp16 copy of W
__device__ int    g_is64;

// ---- bit-pun helpers (union-based) -----------------------------------------
__device__ __forceinline__ uint32_t h2_to_u(__half2 h) {
    union { __half2 h; uint32_t u; } c; c.h = h; return c.u;
}
__device__ __forceinline__ __half2 u_to_h2(uint32_t u) {
    union { uint32_t u; __half2 h; } c; c.u = u; return c.h;
}

// ---------------------------------------------------------------------------
// Kernel 1 (R7 version, best measured): one warp per TWO rows, 6 LDG.128.
// ---------------------------------------------------------------------------
__global__ void bond_kernel(const float* __restrict__ bond,
                            const int* __restrict__ adj_raw) {
    if (blockIdx.x == 0 && threadIdx.x < 32) {
        int lane = threadIdx.x;
        bool odd_zero = true;
        #pragma unroll
        for (int j = 0; j < 32; j++) {
            int pair = lane + 32 * j;
            if (adj_raw[2 * pair + 1] != 0) odd_zero = false;
        }
        bool all = __all_sync(0xffffffffu, odd_zero);
        if (lane == 0) g_is64 = all ? 1 : 0;
    }

    int warp = (blockIdx.x * blockDim.x + threadIdx.x) >> 5;
    int lane = threadIdx.x & 31;
    int row0 = warp * 2;
    if (row0 >= BB * NN) return;

    const float4* p0 = (const float4*)(bond + (size_t)row0 * (MM * 32));
    const float4* p1 = p0 + MM * 32 / 4;
    float4 a0 = p0[lane];
    float4 a1 = p0[lane + 32];
    float4 a2 = p0[lane + 64];
    float4 b0 = p1[lane];
    float4 b1 = p1[lane + 32];
    float4 b2 = p1[lane + 64];

    float qa0 = a0.x*a0.x + a0.y*a0.y + a0.z*a0.z + a0.w*a0.w;
    float qa1 = a1.x*a1.x + a1.y*a1.y + a1.z*a1.z + a1.w*a1.w;
    float qa2 = a2.x*a2.x + a2.y*a2.y + a2.z*a2.z + a2.w*a2.w;
    float qb0 = b0.x*b0.x + b0.y*b0.y + b0.z*b0.z + b0.w*b0.w;
    float qb1 = b1.x*b1.x + b1.y*b1.y + b1.z*b1.z + b1.w*b1.w;
    float qb2 = b2.x*b2.x + b2.y*b2.y + b2.z*b2.z + b2.w*b2.w;

    #pragma unroll
    for (int o = 4; o >= 1; o >>= 1) {
        qa0 += __shfl_xor_sync(0xffffffffu, qa0, o, 8);
        qa1 += __shfl_xor_sync(0xffffffffu, qa1, o, 8);
        qa2 += __shfl_xor_sync(0xffffffffu, qa2, o, 8);
        qb0 += __shfl_xor_sync(0xffffffffu, qb0, o, 8);
        qb1 += __shfl_xor_sync(0xffffffffu, qb1, o, 8);
        qb2 += __shfl_xor_sync(0xffffffffu, qb2, o, 8);
    }
    float xa0 = 1.0f/qa0, xa1 = 1.0f/qa1, xa2 = 1.0f/qa2;
    float xb0 = 1.0f/qb0, xb1 = 1.0f/qb1, xb2 = 1.0f/qb2;

    float sa = xa0 + xa1 + xa2,  pa = xa0 * xa1 * xa2;
    float sb = xb0 + xb1 + xb2,  pb = xb0 * xb1 * xb2;
    sa += __shfl_xor_sync(0xffffffffu, sa, 8);
    sb += __shfl_xor_sync(0xffffffffu, sb, 8);
    sa += __shfl_xor_sync(0xffffffffu, sa, 16);
    sb += __shfl_xor_sync(0xffffffffu, sb, 16);
    pa *= __shfl_xor_sync(0xffffffffu, pa, 8);
    pb *= __shfl_xor_sync(0xffffffffu, pb, 8);
    pa *= __shfl_xor_sync(0xffffffffu, pa, 16);
    pb *= __shfl_xor_sync(0xffffffffu, pb, 16);

    sa = fmaxf(sa, 1e-12f);
    sb = fmaxf(sb, 1e-12f);
    float sa2 = sa*sa, sa4 = sa2*sa2, sa8 = sa4*sa4;
    float sb2 = sb*sb, sb4 = sb2*sb2, sb8 = sb4*sb4;
    if (lane == 0) {
        g_bn3[row0]     = pa / (sa8 * sa4);
        g_bn3[row0 + 1] = pb / (sb8 * sb4);
    }
}

// ---------------------------------------------------------------------------
// Kernel 2 (unchanged): normalize over B, invert, normalize over N.
// ---------------------------------------------------------------------------
__global__ void norm_kernel() {
    int b = blockIdx.x;
    int n = threadIdx.x;

    float csum = 0.0f;
    #pragma unroll
    for (int bb = 0; bb < BB; bb++) csum += fabsf(g_bn3[bb * NN + n]);
    csum = fmaxf(csum, 1e-12f);

    float bn4 = g_bn3[b * NN + n] / csum;
    float bn5 = 1.0f / bn4;

    float r = fabsf(bn5);
    #pragma unroll
    for (int o = 16; o >= 1; o >>= 1) r += __shfl_xor_sync(0xffffffffu, r, o, 32);

    __shared__ float part[32];
    __shared__ float total;
    int wid = threadIdx.x >> 5, lane = threadIdx.x & 31;
    if (lane == 0) part[wid] = r;
    __syncthreads();
    if (wid == 0) {
        float v = part[lane];
        #pragma unroll
        for (int o = 16; o >= 1; o >>= 1) v += __shfl_xor_sync(0xffffffffu, v, o, 32);
        if (lane == 0) total = fmaxf(v, 1e-12f);
    }
    __syncthreads();

    g_bn6[b * NN + n] = bn5 / total;
}

// ---------------------------------------------------------------------------
// Kernel 2b: prep — convert atom and W to fp16 (separate kernel; fusing into
// bond regresses, measured R13).
// ---------------------------------------------------------------------------
__global__ void prep_kernel(const float* __restrict__ atom,
                            const float* __restrict__ W) {
    int bid = blockIdx.x;
    if (bid < 1024) {
        int base = bid * 2048 + threadIdx.x * 8;
        float4 f0 = *(const float4*)(atom + base);
        float4 f1 = *(const float4*)(atom + base + 4);
        uint4 packed;
        packed.x = h2_to_u(__floats2half2_rn(f0.x, f0.y));
        packed.y = h2_to_u(__floats2half2_rn(f0.z, f0.w));
        packed.z = h2_to_u(__floats2half2_rn(f1.x, f1.y));
        packed.w = h2_to_u(__floats2half2_rn(f1.z, f1.w));
        *(uint4*)(g_atom_h + base) = packed;
    } else {
        int i = (bid - 1024) * 256 + threadIdx.x;
        g_Wh[i] = __float2half_rn(W[i]);
    }
}

// ---------------------------------------------------------------------------
// Kernel 3 (v4): 128-row CTA, 1024 threads (32 warps -> 8/SMSP).
// Grid (8,16) = 128 CTAs = one per SM, one wave; per-b L2 slab locality.
// Warp w gathers rows 4w..4w+3 and consumes exactly those rows in Phase B
// (lane>>4 selects the 2-row half) -> __syncwarp between phases.
// GEMM: thread = 2 rows x 8 cols; per 4-k chunk: 6 LDS.128 + 32 HFMA2.
// ---------------------------------------------------------------------------
#define SM_W_BYTES (FA * FO * 2)            // 32 KB
#define SM_U_BYTES (128 * FA * 4)           // 64 KB (dup pairs, 512 B/row)
#define SMEM_TOTAL (SM_W_BYTES + SM_U_BYTES)

__global__ void __launch_bounds__(1024)
main_kernel(const int* __restrict__ adj,
            const float* __restrict__ bias,
            float* __restrict__ out) {
    extern __shared__ char smem[];
    __half* sWh = (__half*)smem;                        // [k][j], 256 B/row
    char*   sU  = smem + SM_W_BYTES;                    // dup-pair rows, 512 B each

    int b   = blockIdx.y;
    int n0  = blockIdx.x * 128;
    int tid = threadIdx.x;
    int wid = tid >> 5, lane = tid & 31;
    int stride = g_is64 ? 2 : 1;

    // Load W(half) into smem: 32 KB = 2048 uint4, 2 per thread
    {
        const uint4* src = (const uint4*)g_Wh;
        uint4* dst = (uint4*)sWh;
        #pragma unroll
        for (int i = 0; i < 2; i++) dst[tid + i * 1024] = src[tid + i * 1024];
    }
    __syncthreads();

    // ---- Phase A: warp w gathers rows 4w..4w+3, writes dup-pair half2 rows
    {
        const __half* atomBh = g_atom_h + (size_t)b * NN * FA;
        const __half2 inv12h = __float2half2_rn(1.0f / 12.0f);
        #pragma unroll 2
        for (int i = 0; i < 4; i++) {
            int r = wid * 4 + i;
            int n = n0 + r;
            const int* adjr = adj + (size_t)(b * NN + n) * MM * stride;
            uint2 selfw = *(const uint2*)(atomBh + (size_t)n * FA + lane * 4);
            __half2 a0 = u_to_h2(selfw.x);
            __half2 a1 = u_to_h2(selfw.y);
            __half2 s0 = __float2half2_rn(0.0f);
            __half2 s1 = __float2half2_rn(0.0f);
            #pragma unroll
            for (int m = 0; m < MM; m++) {
                int idx = adjr[m * stride] & (NN - 1);
                uint2 vw = *(const uint2*)(atomBh + (size_t)idx * FA + lane * 4);
                s0 = __hadd2(s0, u_to_h2(vw.x));
                s1 = __hadd2(s1, u_to_h2(vw.y));
            }
            __half2 bnh = __float2half2_rn(g_bn6[b * NN + n]);
            __half2 u0 = __hmul2(__hfma2(s0, inv12h, a0), bnh);
            __half2 u1 = __hmul2(__hfma2(s1, inv12h, a1), bnh);
            uint4 dupw;
            dupw.x = h2_to_u(__half2half2(__low2half(u0)));
            dupw.y = h2_to_u(__half2half2(__high2half(u0)));
            dupw.z = h2_to_u(__half2half2(__low2half(u1)));
            dupw.w = h2_to_u(__half2half2(__high2half(u1)));
            *(uint4*)(sU + (size_t)r * 512 + lane * 16) = dupw;
        }
    }
    __syncwarp();

    // ---- Phase B: HFMA2 GEMM, 2 rows x 8 cols per thread
    int r0 = wid * 4 + (lane >> 4) * 2;   // rows within this warp's 4
    int tx = lane & 15;
    int c0 = tx * 8;

    __half2 acc[2][4];
    #pragma unroll
    for (int i = 0; i < 2; i++)
        #pragma unroll
        for (int j = 0; j < 4; j++) acc[i][j] = __float2half2_rn(0.0f);

    #pragma unroll 4
    for (int k0 = 0; k0 < FA; k0 += 4) {
        uint32_t wv[4][4];
        #pragma unroll
        for (int kk = 0; kk < 4; kk++) {
            uint4 t = *(const uint4*)((const char*)sWh + (size_t)(k0 + kk) * 256 + tx * 16);
            wv[kk][0] = t.x; wv[kk][1] = t.y; wv[kk][2] = t.z; wv[kk][3] = t.w;
        }
        #pragma unroll
        for (int i = 0; i < 2; i++) {
            uint4 uv = *(const uint4*)(sU + (size_t)(r0 + i) * 512 + k0 * 4);
            uint32_t ud[4] = {uv.x, uv.y, uv.z, uv.w};
            #pragma unroll
            for (int kk = 0; kk < 4; kk++) {
                __half2 u2 = u_to_h2(ud[kk]);
                acc[i][0] = __hfma2(u2, u_to_h2(wv[kk][0]), acc[i][0]);
                acc[i][1] = __hfma2(u2, u_to_h2(wv[kk][1]), acc[i][1]);
                acc[i][2] = __hfma2(u2, u_to_h2(wv[kk][2]), acc[i][2]);
                acc[i][3] = __hfma2(u2, u_to_h2(wv[kk][3]), acc[i][3]);
            }
        }
    }

    // Epilogue: fp32 bias + relu + coalesced float4 stores
    float4 bi0 = *(const float4*)(bias + c0);
    float4 bi1 = *(const float4*)(bias + c0 + 4);

    #pragma unroll
    for (int i = 0; i < 2; i++) {
        int n = n0 + r0 + i;
        float2 p0 = __half22float2(acc[i][0]);
        float2 p1 = __half22float2(acc[i][1]);
        float2 p2 = __half22float2(acc[i][2]);
        float2 p3 = __half22float2(acc[i][3]);
        float4 o0, o1;
        o0.x = fmaxf(p0.x + bi0.x, 0.0f);
        o0.y = fmaxf(p0.y + bi0.y, 0.0f);
        o0.z = fmaxf(p1.x + bi0.z, 0.0f);
        o0.w = fmaxf(p1.y + bi0.w, 0.0f);
        o1.x = fmaxf(p2.x + bi1.x, 0.0f);
        o1.y = fmaxf(p2.y + bi1.y, 0.0f);
        o1.z = fmaxf(p3.x + bi1.z, 0.0f);
        o1.w = fmaxf(p3.y + bi1.w, 0.0f);
        float* op = out + (size_t)(b * NN + n) * FO + c0;
        *(float4*)(op)     = o0;
        *(float4*)(op + 4) = o1;
    }
}

// ---------------------------------------------------------------------------
extern "C" void kernel_launch(void* const* d_in, const int* in_sizes, int n_in,
                              void* d_out, int out_size) {
    const float* atom = (const float*)d_in[0];
    const float* bond = (const float*)d_in[1];
    const int*   adj  = (const int*)d_in[2];
    const float* W    = (const float*)d_in[3];
    const float* bias = (const float*)d_in[4];
    float*       out  = (float*)d_out;

    bond_kernel<<<1024, 256>>>(bond, adj);
    prep_kernel<<<1088, 256>>>(atom, W);
    norm_kernel<<<BB, NN>>>();

    cudaFuncSetAttribute(main_kernel, cudaFuncAttributeMaxDynamicSharedMemorySize,
                         SMEM_TOTAL);
    main_kernel<<<dim3(8, BB), 1024, SMEM_TOTAL>>>(adj, bias, out);
}

// round 17
// speedup vs baseline: 1.1604x; 1.1604x over previous
#include <cuda_runtime.h>
#include <cuda_fp16.h>
#include <cstdint>

#define BB 16
#define NN 1024
#define MM 12
#define FA 128
#define FO 128

// Scratch (allocation-free rule: __device__ globals)
__device__ float  g_bn3[BB * NN];
__device__ float  g_bn6[BB * NN];
__device__ __half g_atom_h[BB * NN * FA];   // 4 MB fp16 copy of atom
__device__ __half g_Wh[FA * FO];            // fp16 copy of W
__device__ int    g_is64;

// ---- bit-pun helpers (union-based) -----------------------------------------
__device__ __forceinline__ uint32_t h2_to_u(__half2 h) {
    union { __half2 h; uint32_t u; } c; c.h = h; return c.u;
}
__device__ __forceinline__ __half2 u_to_h2(uint32_t u) {
    union { uint32_t u; __half2 h; } c; c.u = u; return c.h;
}

// ---------------------------------------------------------------------------
// Kernel 1 (R7 version, best measured): one warp per TWO rows, 6 LDG.128.
// ---------------------------------------------------------------------------
__global__ void bond_kernel(const float* __restrict__ bond,
                            const int* __restrict__ adj_raw) {
    if (blockIdx.x == 0 && threadIdx.x < 32) {
        int lane = threadIdx.x;
        bool odd_zero = true;
        #pragma unroll
        for (int j = 0; j < 32; j++) {
            int pair = lane + 32 * j;
            if (adj_raw[2 * pair + 1] != 0) odd_zero = false;
        }
        bool all = __all_sync(0xffffffffu, odd_zero);
        if (lane == 0) g_is64 = all ? 1 : 0;
    }

    int warp = (blockIdx.x * blockDim.x + threadIdx.x) >> 5;
    int lane = threadIdx.x & 31;
    int row0 = warp * 2;
    if (row0 >= BB * NN) return;

    const float4* p0 = (const float4*)(bond + (size_t)row0 * (MM * 32));
    const float4* p1 = p0 + MM * 32 / 4;
    float4 a0 = p0[lane];
    float4 a1 = p0[lane + 32];
    float4 a2 = p0[lane + 64];
    float4 b0 = p1[lane];
    float4 b1 = p1[lane + 32];
    float4 b2 = p1[lane + 64];

    float qa0 = a0.x*a0.x + a0.y*a0.y + a0.z*a0.z + a0.w*a0.w;
    float qa1 = a1.x*a1.x + a1.y*a1.y + a1.z*a1.z + a1.w*a1.w;
    float qa2 = a2.x*a2.x + a2.y*a2.y + a2.z*a2.z + a2.w*a2.w;
    float qb0 = b0.x*b0.x + b0.y*b0.y + b0.z*b0.z + b0.w*b0.w;
    float qb1 = b1.x*b1.x + b1.y*b1.y + b1.z*b1.z + b1.w*b1.w;
    float qb2 = b2.x*b2.x + b2.y*b2.y + b2.z*b2.z + b2.w*b2.w;

    #pragma unroll
    for (int o = 4; o >= 1; o >>= 1) {
        qa0 += __shfl_xor_sync(0xffffffffu, qa0, o, 8);
        qa1 += __shfl_xor_sync(0xffffffffu, qa1, o, 8);
        qa2 += __shfl_xor_sync(0xffffffffu, qa2, o, 8);
        qb0 += __shfl_xor_sync(0xffffffffu, qb0, o, 8);
        qb1 += __shfl_xor_sync(0xffffffffu, qb1, o, 8);
        qb2 += __shfl_xor_sync(0xffffffffu, qb2, o, 8);
    }
    float xa0 = 1.0f/qa0, xa1 = 1.0f/qa1, xa2 = 1.0f/qa2;
    float xb0 = 1.0f/qb0, xb1 = 1.0f/qb1, xb2 = 1.0f/qb2;

    float sa = xa0 + xa1 + xa2,  pa = xa0 * xa1 * xa2;
    float sb = xb0 + xb1 + xb2,  pb = xb0 * xb1 * xb2;
    sa += __shfl_xor_sync(0xffffffffu, sa, 8);
    sb += __shfl_xor_sync(0xffffffffu, sb, 8);
    sa += __shfl_xor_sync(0xffffffffu, sa, 16);
    sb += __shfl_xor_sync(0xffffffffu, sb, 16);
    pa *= __shfl_xor_sync(0xffffffffu, pa, 8);
    pb *= __shfl_xor_sync(0xffffffffu, pb, 8);
    pa *= __shfl_xor_sync(0xffffffffu, pa, 16);
    pb *= __shfl_xor_sync(0xffffffffu, pb, 16);

    sa = fmaxf(sa, 1e-12f);
    sb = fmaxf(sb, 1e-12f);
    float sa2 = sa*sa, sa4 = sa2*sa2, sa8 = sa4*sa4;
    float sb2 = sb*sb, sb4 = sb2*sb2, sb8 = sb4*sb4;
    if (lane == 0) {
        g_bn3[row0]     = pa / (sa8 * sa4);
        g_bn3[row0 + 1] = pb / (sb8 * sb4);
    }
}

// ---------------------------------------------------------------------------
// Kernel 2 (unchanged): normalize over B, invert, normalize over N.
// ---------------------------------------------------------------------------
__global__ void norm_kernel() {
    int b = blockIdx.x;
    int n = threadIdx.x;

    float csum = 0.0f;
    #pragma unroll
    for (int bb = 0; bb < BB; bb++) csum += fabsf(g_bn3[bb * NN + n]);
    csum = fmaxf(csum, 1e-12f);

    float bn4 = g_bn3[b * NN + n] / csum;
    float bn5 = 1.0f / bn4;

    float r = fabsf(bn5);
    #pragma unroll
    for (int o = 16; o >= 1; o >>= 1) r += __shfl_xor_sync(0xffffffffu, r, o, 32);

    __shared__ float part[32];
    __shared__ float total;
    int wid = threadIdx.x >> 5, lane = threadIdx.x & 31;
    if (lane == 0) part[wid] = r;
    __syncthreads();
    if (wid == 0) {
        float v = part[lane];
        #pragma unroll
        for (int o = 16; o >= 1; o >>= 1) v += __shfl_xor_sync(0xffffffffu, v, o, 32);
        if (lane == 0) total = fmaxf(v, 1e-12f);
    }
    __syncthreads();

    g_bn6[b * NN + n] = bn5 / total;
}

// ---------------------------------------------------------------------------
// Kernel 2b: prep — convert atom and W to fp16 (separate; fusing regresses).
// ---------------------------------------------------------------------------
__global__ void prep_kernel(const float* __restrict__ atom,
                            const float* __restrict__ W) {
    int bid = blockIdx.x;
    if (bid < 1024) {
        int base = bid * 2048 + threadIdx.x * 8;
        float4 f0 = *(const float4*)(atom + base);
        float4 f1 = *(const float4*)(atom + base + 4);
        uint4 packed;
        packed.x = h2_to_u(__floats2half2_rn(f0.x, f0.y));
        packed.y = h2_to_u(__floats2half2_rn(f0.z, f0.w));
        packed.z = h2_to_u(__floats2half2_rn(f1.x, f1.y));
        packed.w = h2_to_u(__floats2half2_rn(f1.z, f1.w));
        *(uint4*)(g_atom_h + base) = packed;
    } else {
        int i = (bid - 1024) * 256 + threadIdx.x;
        g_Wh[i] = __float2half_rn(W[i]);
    }
}

// ---------------------------------------------------------------------------
// Kernel 3 (v5): 128-row CTA, 512 threads (16 warps, best measured), with
// EXPLICIT double-buffered Phase B: chunk c+1's LDS issue before chunk c's
// HFMA2 stream -> LDS latency hidden by FMA work, FMA-bound steady state.
// Warp w gathers rows 8w..8w+7, consumes exactly those rows in Phase B.
// ---------------------------------------------------------------------------
#define SM_W_BYTES (FA * FO * 2)            // 32 KB
#define SM_U_BYTES (128 * FA * 4)           // 64 KB (dup pairs, 512 B/row)
#define SMEM_TOTAL (SM_W_BYTES + SM_U_BYTES)

__global__ void __launch_bounds__(512, 1)
main_kernel(const int* __restrict__ adj,
            const float* __restrict__ bias,
            float* __restrict__ out) {
    extern __shared__ char smem[];
    __half* sWh = (__half*)smem;                        // [k][j], 256 B/row
    char*   sU  = smem + SM_W_BYTES;                    // dup-pair rows, 512 B each

    int b   = blockIdx.y;
    int n0  = blockIdx.x * 128;
    int tid = threadIdx.x;
    int wid = tid >> 5, lane = tid & 31;
    int stride = g_is64 ? 2 : 1;

    // Load W(half) into smem: 32 KB = 2048 uint4, 4 per thread
    {
        const uint4* src = (const uint4*)g_Wh;
        uint4* dst = (uint4*)sWh;
        #pragma unroll
        for (int i = 0; i < 4; i++) dst[tid + i * 512] = src[tid + i * 512];
    }
    __syncthreads();

    // ---- Phase A: warp w gathers rows 8w..8w+7, writes dup-pair half2 rows
    {
        const __half* atomBh = g_atom_h + (size_t)b * NN * FA;
        const __half2 inv12h = __float2half2_rn(1.0f / 12.0f);
        #pragma unroll 2
        for (int i = 0; i < 8; i++) {
            int r = wid * 8 + i;
            int n = n0 + r;
            const int* adjr = adj + (size_t)(b * NN + n) * MM * stride;
            uint2 selfw = *(const uint2*)(atomBh + (size_t)n * FA + lane * 4);
            __half2 a0 = u_to_h2(selfw.x);
            __half2 a1 = u_to_h2(selfw.y);
            __half2 s0 = __float2half2_rn(0.0f);
            __half2 s1 = __float2half2_rn(0.0f);
            #pragma unroll
            for (int m = 0; m < MM; m++) {
                int idx = adjr[m * stride] & (NN - 1);
                uint2 vw = *(const uint2*)(atomBh + (size_t)idx * FA + lane * 4);
                s0 = __hadd2(s0, u_to_h2(vw.x));
                s1 = __hadd2(s1, u_to_h2(vw.y));
            }
            __half2 bnh = __float2half2_rn(g_bn6[b * NN + n]);
            __half2 u0 = __hmul2(__hfma2(s0, inv12h, a0), bnh);
            __half2 u1 = __hmul2(__hfma2(s1, inv12h, a1), bnh);
            uint4 dupw;
            dupw.x = h2_to_u(__half2half2(__low2half(u0)));
            dupw.y = h2_to_u(__half2half2(__high2half(u0)));
            dupw.z = h2_to_u(__half2half2(__low2half(u1)));
            dupw.w = h2_to_u(__half2half2(__high2half(u1)));
            *(uint4*)(sU + (size_t)r * 512 + lane * 16) = dupw;
        }
    }
    __syncwarp();

    // ---- Phase B: HFMA2 GEMM, 4 rows x 8 cols per thread, double-buffered
    int r0 = wid * 8 + (lane >> 4) * 4;   // rows within this warp's 8
    int tx = lane & 15;
    int c0 = tx * 8;

    const char* wptr = (const char*)sWh + tx * 16;   // + k*256
    const char* uptr = sU + (size_t)r0 * 512;        // + i*512 + k*4

    __half2 acc[4][4];
    #pragma unroll
    for (int i = 0; i < 4; i++)
        #pragma unroll
        for (int j = 0; j < 4; j++) acc[i][j] = __float2half2_rn(0.0f);

    uint4 wbuf[2][4];
    uint4 ubuf[2][4];

    // prefetch chunk 0
    #pragma unroll
    for (int kk = 0; kk < 4; kk++)
        wbuf[0][kk] = *(const uint4*)(wptr + (size_t)kk * 256);
    #pragma unroll
    for (int i = 0; i < 4; i++)
        ubuf[0][i] = *(const uint4*)(uptr + (size_t)i * 512);

    #pragma unroll
    for (int c = 0; c < 32; c++) {
        int p = c & 1, q = p ^ 1;
        if (c + 1 < 32) {
            int kn = (c + 1) * 4;
            #pragma unroll
            for (int kk = 0; kk < 4; kk++)
                wbuf[q][kk] = *(const uint4*)(wptr + (size_t)(kn + kk) * 256);
            #pragma unroll
            for (int i = 0; i < 4; i++)
                ubuf[q][i] = *(const uint4*)(uptr + (size_t)i * 512 + kn * 4);
        }
        #pragma unroll
        for (int i = 0; i < 4; i++) {
            uint32_t ud[4] = {ubuf[p][i].x, ubuf[p][i].y, ubuf[p][i].z, ubuf[p][i].w};
            #pragma unroll
            for (int kk = 0; kk < 4; kk++) {
                __half2 u2 = u_to_h2(ud[kk]);
                acc[i][0] = __hfma2(u2, u_to_h2(wbuf[p][kk].x), acc[i][0]);
                acc[i][1] = __hfma2(u2, u_to_h2(wbuf[p][kk].y), acc[i][1]);
                acc[i][2] = __hfma2(u2, u_to_h2(wbuf[p][kk].z), acc[i][2]);
                acc[i][3] = __hfma2(u2, u_to_h2(wbuf[p][kk].w), acc[i][3]);
            }
        }
    }

    // Epilogue: fp32 bias + relu + coalesced float4 stores
    float4 bi0 = *(const float4*)(bias + c0);
    float4 bi1 = *(const float4*)(bias + c0 + 4);

    #pragma unroll
    for (int i = 0; i < 4; i++) {
        int n = n0 + r0 + i;
        float2 p0 = __half22float2(acc[i][0]);
        float2 p1 = __half22float2(acc[i][1]);
        float2 p2 = __half22float2(acc[i][2]);
        float2 p3 = __half22float2(acc[i][3]);
        float4 o0, o1;
        o0.x = fmaxf(p0.x + bi0.x, 0.0f);
        o0.y = fmaxf(p0.y + bi0.y, 0.0f);
        o0.z = fmaxf(p1.x + bi0.z, 0.0f);
        o0.w = fmaxf(p1.y + bi0.w, 0.0f);
        o1.x = fmaxf(p2.x + bi1.x, 0.0f);
        o1.y = fmaxf(p2.y + bi1.y, 0.0f);
        o1.z = fmaxf(p3.x + bi1.z, 0.0f);
        o1.w = fmaxf(p3.y + bi1.w, 0.0f);
        float* op = out + (size_t)(b * NN + n) * FO + c0;
        *(float4*)(op)     = o0;
        *(float4*)(op + 4) = o1;
    }
}

// ---------------------------------------------------------------------------
extern "C" void kernel_launch(void* const* d_in, const int* in_sizes, int n_in,
                              void* d_out, int out_size) {
    const float* atom = (const float*)d_in[0];
    const float* bond = (const float*)d_in[1];
    const int*   adj  = (const int*)d_in[2];
    const float* W    = (const float*)d_in[3];
    const float* bias = (const float*)d_in[4];
    float*       out  = (float*)d_out;

    bond_kernel<<<1024, 256>>>(bond, adj);
    prep_kernel<<<1088, 256>>>(atom, W);
    norm_kernel<<<BB, NN>>>();

    cudaFuncSetAttribute(main_kernel, cudaFuncAttributeMaxDynamicSharedMemorySize,
                         SMEM_TOTAL);
    main_kernel<<<dim3(8, BB), 512, SMEM_TOTAL>>>(adj, bias, out);
}